// round 3
// baseline (speedup 1.0000x reference)
#include <cuda_runtime.h>
#include <math.h>

#define H   256
#define S   8     // samples per block
#define TPB 128   // each thread owns columns j and j+128

// Dynamic shared memory layout:
//   ulonglong2 sa2[S][H] : packed {h,g0 | g1,g2}
//   ulonglong2 sb2[S][H] : packed {s0,s1 | s2,0}
//   float      red[S][4][8]
#define SMEM_BYTES (2 * S * H * 16 + S * 4 * 8 * 4)

typedef unsigned long long u64;

__device__ __forceinline__ u64 pack2(float lo, float hi) {
    u64 r; asm("mov.b64 %0,{%1,%2};" : "=l"(r) : "f"(lo), "f"(hi)); return r;
}
__device__ __forceinline__ void unpack2(u64 v, float& lo, float& hi) {
    asm("mov.b64 {%0,%1},%2;" : "=f"(lo), "=f"(hi) : "l"(v));
}
__device__ __forceinline__ u64 fma2(u64 a, u64 b, u64 c) {
    u64 d; asm("fma.rn.f32x2 %0,%1,%2,%3;" : "=l"(d) : "l"(a), "l"(b), "l"(c)); return d;
}

__device__ __forceinline__ float my_tanhf(float z) {
    float a = fabsf(z);
    float e = __expf(-2.0f * a);
    float t = __fdividef(1.0f - e, 1.0f + e);
    return copysignf(t, z);
}

// z-jets -> activation jets: out = {h, t*g0, t*g1, t*g2, s0', s1', s2'}
__device__ __forceinline__ void act_jets(u64 z01, u64 z23, u64 z45, u64 z6p, float out[7]) {
    float zh, zg0, zg1, zg2, zs0, zs1, zs2, dummy;
    unpack2(z01, zh, zg0); unpack2(z23, zg1, zg2);
    unpack2(z45, zs0, zs1); unpack2(z6p, zs2, dummy);
    float h = my_tanhf(zh);
    float t = 1.0f - h * h;
    float c = -2.0f * h * t;
    out[0] = h;
    out[1] = t * zg0; out[2] = t * zg1; out[3] = t * zg2;
    out[4] = fmaf(c * zg0, zg0, t * zs0);
    out[5] = fmaf(c * zg1, zg1, t * zs1);
    out[6] = fmaf(c * zg2, zg2, t * zs2);
}

__global__ __launch_bounds__(TPB, 2) void pinn_jet2_kernel(
    const float* __restrict__ x,
    const float* __restrict__ W0, const float* __restrict__ b0,
    const float* __restrict__ W1, const float* __restrict__ b1,
    const float* __restrict__ W2, const float* __restrict__ b2,
    const float* __restrict__ W3, const float* __restrict__ b3,
    const float* __restrict__ Wout, const float* __restrict__ bout,
    float* __restrict__ out, int B)
{
    extern __shared__ float smem_raw[];
    ulonglong2* sa2 = (ulonglong2*)smem_raw;   // [S][H]
    ulonglong2* sb2 = sa2 + S * H;             // [S][H]
    float*      red = (float*)(sb2 + S * H);   // [S][4][8]

    const int j    = threadIdx.x;        // column A
    const int j2   = j + TPB;            // column B
    const int base = blockIdx.x * S;

    // ---------------- layer 0: x[3] -> jets for cols j and j2 -------------
    {
        const float wax = W0[j],       way = W0[H + j],   waz = W0[2 * H + j];
        const float wbx = W0[j2],      wby = W0[H + j2],  wbz = W0[2 * H + j2];
        const float ba  = b0[j],       bb  = b0[j2];
        #pragma unroll
        for (int s = 0; s < S; s++) {
            int idx = base + s; if (idx >= B) idx = B - 1;
            float x0 = __ldg(&x[idx * 3 + 0]);
            float x1 = __ldg(&x[idx * 3 + 1]);
            float x2 = __ldg(&x[idx * 3 + 2]);
            // column A
            float z = fmaf(x2, waz, fmaf(x1, way, fmaf(x0, wax, ba)));
            float h = my_tanhf(z), t = 1.0f - h * h, c = -2.0f * h * t;
            sa2[s * H + j]  = make_ulonglong2(pack2(h, t * wax), pack2(t * way, t * waz));
            sb2[s * H + j]  = make_ulonglong2(pack2(c * wax * wax, c * way * way),
                                              pack2(c * waz * waz, 0.0f));
            // column B
            z = fmaf(x2, wbz, fmaf(x1, wby, fmaf(x0, wbx, bb)));
            h = my_tanhf(z); t = 1.0f - h * h; c = -2.0f * h * t;
            sa2[s * H + j2] = make_ulonglong2(pack2(h, t * wbx), pack2(t * wby, t * wbz));
            sb2[s * H + j2] = make_ulonglong2(pack2(c * wbx * wbx, c * wby * wby),
                                              pack2(c * wbz * wbz, 0.0f));
        }
    }
    __syncthreads();

    // ---------------- hidden layers 1..3 ----------------------------------
    const float* Ws[3] = {W1, W2, W3};
    const float* bs[3] = {b1, b2, b3};

    #pragma unroll 1
    for (int l = 0; l < 3; l++) {
        const float* __restrict__ W = Ws[l];
        const float bla = __ldg(&bs[l][j]);
        const float blb = __ldg(&bs[l][j2]);

        // z-jet accumulators: 4 packed pairs per (sample, column)
        u64 a0[S], a1[S], a2[S], a3[S];     // column A
        u64 c0[S], c1[S], c2[S], c3[S];     // column B
        #pragma unroll
        for (int s = 0; s < S; s++) {
            a0[s] = pack2(bla, 0.0f); a1[s] = 0ull; a2[s] = 0ull; a3[s] = 0ull;
            c0[s] = pack2(blb, 0.0f); c1[s] = 0ull; c2[s] = 0ull; c3[s] = 0ull;
        }

        float wa = __ldg(&W[j]);
        float wb = __ldg(&W[j2]);
        for (int k = 0; k < H; k++) {
            float wan = (k + 1 < H) ? __ldg(&W[(k + 1) * H + j])  : 0.0f;
            float wbn = (k + 1 < H) ? __ldg(&W[(k + 1) * H + j2]) : 0.0f;
            u64 wa2 = pack2(wa, wa);
            u64 wb2 = pack2(wb, wb);
            #pragma unroll
            for (int s = 0; s < S; s++) {
                ulonglong2 A  = sa2[s * H + k];   // broadcast LDS.128
                ulonglong2 Bv = sb2[s * H + k];   // broadcast LDS.128
                a0[s] = fma2(wa2, A.x,  a0[s]);
                a1[s] = fma2(wa2, A.y,  a1[s]);
                a2[s] = fma2(wa2, Bv.x, a2[s]);
                a3[s] = fma2(wa2, Bv.y, a3[s]);
                c0[s] = fma2(wb2, A.x,  c0[s]);
                c1[s] = fma2(wb2, A.y,  c1[s]);
                c2[s] = fma2(wb2, Bv.x, c2[s]);
                c3[s] = fma2(wb2, Bv.y, c3[s]);
            }
            wa = wan; wb = wbn;
        }

        if (l < 2) {
            __syncthreads();
            #pragma unroll
            for (int s = 0; s < S; s++) {
                float fa[7], fb[7];
                act_jets(a0[s], a1[s], a2[s], a3[s], fa);
                act_jets(c0[s], c1[s], c2[s], c3[s], fb);
                sa2[s * H + j]  = make_ulonglong2(pack2(fa[0], fa[1]), pack2(fa[2], fa[3]));
                sb2[s * H + j]  = make_ulonglong2(pack2(fa[4], fa[5]), pack2(fa[6], 0.0f));
                sa2[s * H + j2] = make_ulonglong2(pack2(fb[0], fb[1]), pack2(fb[2], fb[3]));
                sb2[s * H + j2] = make_ulonglong2(pack2(fb[4], fb[5]), pack2(fb[6], 0.0f));
            }
            __syncthreads();
        } else {
            // ---------------- output head fused into last layer -----------
            const float woa = __ldg(&Wout[j]);
            const float wob = __ldg(&Wout[j2]);
            const int lane  = j & 31;
            const int warp  = j >> 5;

            #pragma unroll
            for (int s = 0; s < S; s++) {
                float fa[7], fb[7], p[7];
                act_jets(a0[s], a1[s], a2[s], a3[s], fa);
                act_jets(c0[s], c1[s], c2[s], c3[s], fb);
                #pragma unroll
                for (int c = 0; c < 7; c++) p[c] = fmaf(fa[c], woa, fb[c] * wob);
                #pragma unroll
                for (int off = 16; off > 0; off >>= 1) {
                    #pragma unroll
                    for (int c = 0; c < 7; c++)
                        p[c] += __shfl_down_sync(0xffffffffu, p[c], off);
                }
                if (lane == 0) {
                    float* r = red + (s * 4 + warp) * 8;
                    #pragma unroll
                    for (int c = 0; c < 7; c++) r[c] = p[c];
                }
            }
            __syncthreads();

            if (j < S * 7) {
                int s = j / 7, c = j % 7;
                int idx = base + s;
                if (idx < B) {
                    float v = red[(s * 4 + 0) * 8 + c] + red[(s * 4 + 1) * 8 + c]
                            + red[(s * 4 + 2) * 8 + c] + red[(s * 4 + 3) * 8 + c];
                    if (c == 0) v += __ldg(&bout[0]);
                    out[idx * 7 + c] = v;
                }
            }
        }
    }
}

extern "C" void kernel_launch(void* const* d_in, const int* in_sizes, int n_in,
                              void* d_out, int out_size)
{
    const float* x    = (const float*)d_in[0];
    const float* W0   = (const float*)d_in[1];
    const float* b0   = (const float*)d_in[2];
    const float* W1   = (const float*)d_in[3];
    const float* b1   = (const float*)d_in[4];
    const float* W2   = (const float*)d_in[5];
    const float* b2   = (const float*)d_in[6];
    const float* W3   = (const float*)d_in[7];
    const float* b3   = (const float*)d_in[8];
    const float* Wout = (const float*)d_in[9];
    const float* bout = (const float*)d_in[10];
    float* out = (float*)d_out;

    const int B = in_sizes[0] / 3;
    const int nblk = (B + S - 1) / S;

    cudaFuncSetAttribute(pinn_jet2_kernel,
                         cudaFuncAttributeMaxDynamicSharedMemorySize, SMEM_BYTES);
    pinn_jet2_kernel<<<nblk, TPB, SMEM_BYTES>>>(x, W0, b0, W1, b1, W2, b2, W3, b3,
                                                Wout, bout, out, B);
}

// round 5
// speedup vs baseline: 1.6565x; 1.6565x over previous
#include <cuda_runtime.h>
#include <cuda_bf16.h>
#include <cstdint>
#include <math.h>

#define HID 256
#define SPB 16          // samples per block -> M = 128 jet rows
#define TPB 512         // 16 warps

#define RSA 528         // A smem row stride in bytes (264 bf16: 256 + 8 pad)
#define RSW 80          // W chunk smem row stride in bytes (40 bf16: 32 + 8 pad)

// ---- dynamic smem offsets (bytes) ----
#define SM_RED   0                          // 256 floats
#define SM_AH    1024
#define SM_AL    (SM_AH + 128 * RSA)        // 68608
#define SM_W     (SM_AL + 128 * RSA)        // 136192
#define WBUF_SZ  (2 * 256 * RSW)            // 40960 (hi + lo planes)
#define SMEM_TOTAL (SM_W + 2 * WBUF_SZ)     // 218112

// pre-transposed hi/lo weights: g_wt[layer][part][n*256 + k]  (WT[n][k] = W[k][n])
__device__ __align__(16) __nv_bfloat16 g_wt[3][2][HID * HID];

// ---------------- helpers ----------------
__device__ __forceinline__ uint32_t smem_u32(const void* p) {
    uint32_t a;
    asm("{ .reg .u64 t; cvta.to.shared.u64 t, %1; cvt.u32.u64 %0, t; }" : "=r"(a) : "l"(p));
    return a;
}
__device__ __forceinline__ void ldsm_x4(uint32_t addr, uint32_t r[4]) {
    asm volatile("ldmatrix.sync.aligned.m8n8.x4.shared.b16 {%0,%1,%2,%3}, [%4];"
                 : "=r"(r[0]), "=r"(r[1]), "=r"(r[2]), "=r"(r[3]) : "r"(addr));
}
__device__ __forceinline__ void mma16816(float d[4], const uint32_t a[4],
                                         uint32_t b0, uint32_t b1) {
    asm volatile("mma.sync.aligned.m16n8k16.row.col.f32.bf16.bf16.f32 "
                 "{%0,%1,%2,%3},{%4,%5,%6,%7},{%8,%9},{%0,%1,%2,%3};"
                 : "+f"(d[0]), "+f"(d[1]), "+f"(d[2]), "+f"(d[3])
                 : "r"(a[0]), "r"(a[1]), "r"(a[2]), "r"(a[3]), "r"(b0), "r"(b1));
}
__device__ __forceinline__ void cp16(uint32_t dst, const void* src) {
    asm volatile("cp.async.ca.shared.global [%0], [%1], 16;" :: "r"(dst), "l"(src));
}
#define CP_COMMIT() asm volatile("cp.async.commit_group;" ::: "memory")
#define CP_WAIT0()  asm volatile("cp.async.wait_group 0;" ::: "memory")

__device__ __forceinline__ float my_tanhf(float z) {
    float a = fabsf(z);
    float e = __expf(-2.0f * a);
    float t = __fdividef(1.0f - e, 1.0f + e);
    return copysignf(t, z);
}
__device__ __forceinline__ void split_pack(float a, float b, uint32_t& hi, uint32_t& lo) {
    __nv_bfloat16 ha = __float2bfloat16(a), hb = __float2bfloat16(b);
    __nv_bfloat16 la = __float2bfloat16(a - __bfloat162float(ha));
    __nv_bfloat16 lb = __float2bfloat16(b - __bfloat162float(hb));
    hi = (uint32_t)__bfloat16_as_ushort(ha) | ((uint32_t)__bfloat16_as_ushort(hb) << 16);
    lo = (uint32_t)__bfloat16_as_ushort(la) | ((uint32_t)__bfloat16_as_ushort(lb) << 16);
}
// store bf16 hi/lo pair at A[m][nc], nc even
__device__ __forceinline__ void storeA(char* smem, int m, int nc, float v0, float v1) {
    uint32_t hi, lo; split_pack(v0, v1, hi, lo);
    int off = m * RSA + nc * 2;
    *(uint32_t*)(smem + SM_AH + off) = hi;
    *(uint32_t*)(smem + SM_AL + off) = lo;
}

// ---------------- prep: W[k][n] -> WT[n][k] bf16 hi/lo ----------------
__global__ void prep_w_kernel(const float* __restrict__ W1, const float* __restrict__ W2,
                              const float* __restrict__ W3) {
    int idx = blockIdx.x * blockDim.x + threadIdx.x;
    if (idx >= 3 * HID * HID) return;
    int l = idx >> 16, r = idx & 65535;
    int k = r >> 8, n = r & 255;
    const float* W = (l == 0) ? W1 : (l == 1) ? W2 : W3;
    float v = W[k * HID + n];
    __nv_bfloat16 h = __float2bfloat16(v);
    __nv_bfloat16 lo = __float2bfloat16(v - __bfloat162float(h));
    g_wt[l][0][n * HID + k] = h;
    g_wt[l][1][n * HID + k] = lo;
}

// ---------------- main kernel ----------------
__global__ __launch_bounds__(TPB, 1) void pinn_mma_kernel(
    const float* __restrict__ x,
    const float* __restrict__ W0, const float* __restrict__ b0,
    const float* __restrict__ b1, const float* __restrict__ b2,
    const float* __restrict__ b3,
    const float* __restrict__ Wout, const float* __restrict__ bout,
    float* __restrict__ out, int B)
{
    extern __shared__ char smem[];
    const uint32_t sb = smem_u32(smem);
    const int tid = threadIdx.x, wid = tid >> 5, lane = tid & 31;
    const int base = blockIdx.x * SPB;

    // -------- layer 0: analytic jets -> A (rows m = s*8 + ch) --------
    {
        const int nc = (tid & 127) * 2;
        const int sg = tid >> 7;                 // 4 sample groups of 4
        float wa0 = __ldg(&W0[nc]),     wa1 = __ldg(&W0[HID + nc]),     wa2 = __ldg(&W0[2*HID + nc]);
        float wb0 = __ldg(&W0[nc + 1]), wb1 = __ldg(&W0[HID + nc + 1]), wb2 = __ldg(&W0[2*HID + nc + 1]);
        float ba = __ldg(&b0[nc]), bb = __ldg(&b0[nc + 1]);
        #pragma unroll
        for (int i = 0; i < 4; i++) {
            int s = sg * 4 + i;
            int idx = base + s; if (idx >= B) idx = B - 1;
            float x0 = __ldg(&x[idx*3]), x1 = __ldg(&x[idx*3+1]), x2 = __ldg(&x[idx*3+2]);
            float za = fmaf(x2, wa2, fmaf(x1, wa1, fmaf(x0, wa0, ba)));
            float zb = fmaf(x2, wb2, fmaf(x1, wb1, fmaf(x0, wb0, bb)));
            float hA = my_tanhf(za), tA = 1.f - hA*hA, cA = -2.f*hA*tA;
            float hB = my_tanhf(zb), tB = 1.f - hB*hB, cB = -2.f*hB*tB;
            float va[8] = {hA, tA*wa0, tA*wa1, tA*wa2, cA*wa0*wa0, cA*wa1*wa1, cA*wa2*wa2, 0.f};
            float vb[8] = {hB, tB*wb0, tB*wb1, tB*wb2, cB*wb0*wb0, cB*wb1*wb1, cB*wb2*wb2, 0.f};
            #pragma unroll
            for (int c = 0; c < 8; c++) storeA(smem, s * 8 + c, nc, va[c], vb[c]);
        }
    }
    __syncthreads();

    // warp tiling: warp = m16 x n128
    const int mrow0 = (wid & 7) * 16;
    const int nhalf = (wid >> 3) * 128;
    const int ch = lane >> 2;               // channel 0..7 (rows l/4 and l/4+8)
    const int srcb = lane & 3;              // same-column channel-0 lane
    // A frag lane address: row = mrow0 + (lane&15), khalf byte = (lane>>4)*16
    const uint32_t aOff = (uint32_t)((mrow0 + (lane & 15)) * RSA + (lane >> 4) * 16);
    // B frag lane address: row-in-16 = (lane&7) + ((lane>=16)?8:0), khalf = ((lane>>3)&1)*16
    const uint32_t bOff = (uint32_t)((((lane & 7) + ((lane >> 4) << 3)) * RSW)
                                     + ((lane >> 3) & 1) * 16);

    #pragma unroll 1
    for (int l = 0; l < 3; l++) {
        float acc[16][4];
        #pragma unroll
        for (int nt = 0; nt < 16; nt++)
            { acc[nt][0] = 0.f; acc[nt][1] = 0.f; acc[nt][2] = 0.f; acc[nt][3] = 0.f; }

        #pragma unroll 1
        for (int kc = 0; kc < 8; kc++) {
            if (kc == 0) {
                // synchronous fill of buffer 0
                #pragma unroll
                for (int i = 0; i < 4; i++) {
                    int idx = tid + i * 512;
                    int seg = idx & 3, n = (idx >> 2) & 255, part = idx >> 10;
                    const char* src = (const char*)&g_wt[l][part][n * HID] + seg * 16;
                    cp16(sb + SM_W + part * 20480 + (uint32_t)(n * RSW + seg * 16), src);
                }
                CP_COMMIT(); CP_WAIT0();
                __syncthreads();
            }
            if (kc < 7) {
                // prefetch chunk kc+1 into the other buffer
                uint32_t wdst = sb + SM_W + (uint32_t)(((kc + 1) & 1) * WBUF_SZ);
                #pragma unroll
                for (int i = 0; i < 4; i++) {
                    int idx = tid + i * 512;
                    int seg = idx & 3, n = (idx >> 2) & 255, part = idx >> 10;
                    const char* src = (const char*)&g_wt[l][part][n * HID + (kc + 1) * 32] + seg * 16;
                    cp16(wdst + part * 20480 + (uint32_t)(n * RSW + seg * 16), src);
                }
                CP_COMMIT();
            }
            const uint32_t wb = sb + SM_W + (uint32_t)((kc & 1) * WBUF_SZ);
            #pragma unroll
            for (int ks = 0; ks < 2; ks++) {
                const uint32_t akb = (uint32_t)(kc * 64 + ks * 32);   // A k byte offset
                uint32_t ah[4], al[4];
                ldsm_x4(sb + SM_AH + aOff + akb, ah);
                ldsm_x4(sb + SM_AL + aOff + akb, al);
                #pragma unroll
                for (int nt = 0; nt < 16; nt += 2) {
                    uint32_t bh[4], bl[4];
                    uint32_t wrow = wb + (uint32_t)((nhalf + nt * 8) * RSW) + bOff
                                  + (uint32_t)(ks * 32);
                    ldsm_x4(wrow, bh);
                    ldsm_x4(wrow + 20480, bl);
                    mma16816(acc[nt],     ah, bh[0], bh[1]);
                    mma16816(acc[nt],     al, bh[0], bh[1]);
                    mma16816(acc[nt],     ah, bl[0], bl[1]);
                    mma16816(acc[nt + 1], ah, bh[2], bh[3]);
                    mma16816(acc[nt + 1], al, bh[2], bh[3]);
                    mma16816(acc[nt + 1], ah, bl[2], bl[3]);
                }
            }
            if (kc < 7) { CP_WAIT0(); __syncthreads(); }
        }
        __syncthreads();   // all MMA reads of A done before epilogue overwrites A

        // -------- epilogue: z-jets -> activation jets --------
        const float* bp = (l == 0) ? b1 : (l == 1) ? b2 : b3;
        float accO01 = 0.f, accO23 = 0.f;
        const int gsrc = (lane - 12) & 31;   // hessian source lane (ch-3), junk if ch<4

        #pragma unroll
        for (int nt = 0; nt < 16; nt++) {
            int ncol = nhalf + nt * 8 + (srcb << 1);
            float z0 = acc[nt][0], z1 = acc[nt][1], z2 = acc[nt][2], z3 = acc[nt][3];
            float bi0 = __ldg(&bp[ncol]), bi1 = __ldg(&bp[ncol + 1]);
            float zb0 = __shfl_sync(0xffffffffu, z0, srcb) + bi0;
            float zb1 = __shfl_sync(0xffffffffu, z1, srcb) + bi1;
            float zb2 = __shfl_sync(0xffffffffu, z2, srcb) + bi0;
            float zb3 = __shfl_sync(0xffffffffu, z3, srcb) + bi1;
            float h0 = my_tanhf(zb0), t0 = 1.f - h0*h0, c0 = -2.f*h0*t0;
            float h1 = my_tanhf(zb1), t1 = 1.f - h1*h1, c1 = -2.f*h1*t1;
            float h2 = my_tanhf(zb2), t2 = 1.f - h2*h2, c2 = -2.f*h2*t2;
            float h3 = my_tanhf(zb3), t3 = 1.f - h3*h3, c3 = -2.f*h3*t3;
            float zg0 = __shfl_sync(0xffffffffu, z0, gsrc);
            float zg1 = __shfl_sync(0xffffffffu, z1, gsrc);
            float zg2 = __shfl_sync(0xffffffffu, z2, gsrc);
            float zg3 = __shfl_sync(0xffffffffu, z3, gsrc);
            float o0 = (ch == 0) ? h0 : (ch < 4) ? t0 * z0
                     : (ch < 7) ? fmaf(c0 * zg0, zg0, t0 * z0) : 0.f;
            float o1 = (ch == 0) ? h1 : (ch < 4) ? t1 * z1
                     : (ch < 7) ? fmaf(c1 * zg1, zg1, t1 * z1) : 0.f;
            float o2 = (ch == 0) ? h2 : (ch < 4) ? t2 * z2
                     : (ch < 7) ? fmaf(c2 * zg2, zg2, t2 * z2) : 0.f;
            float o3 = (ch == 0) ? h3 : (ch < 4) ? t3 * z3
                     : (ch < 7) ? fmaf(c3 * zg3, zg3, t3 * z3) : 0.f;
            if (l < 2) {
                storeA(smem, mrow0 + ch,     ncol, o0, o1);
                storeA(smem, mrow0 + ch + 8, ncol, o2, o3);
            } else {
                float w0 = __ldg(&Wout[ncol]), w1 = __ldg(&Wout[ncol + 1]);
                accO01 = fmaf(o0, w0, fmaf(o1, w1, accO01));
                accO23 = fmaf(o2, w0, fmaf(o3, w1, accO23));
            }
        }

        if (l == 2) {
            accO01 += __shfl_xor_sync(0xffffffffu, accO01, 1);
            accO01 += __shfl_xor_sync(0xffffffffu, accO01, 2);
            accO23 += __shfl_xor_sync(0xffffffffu, accO23, 1);
            accO23 += __shfl_xor_sync(0xffffffffu, accO23, 2);
            float* red = (float*)(smem + SM_RED);
            if (srcb == 0) {
                red[(wid >> 3) * 128 + mrow0 + ch]     = accO01;
                red[(wid >> 3) * 128 + mrow0 + ch + 8] = accO23;
            }
            __syncthreads();
            if (tid < 128) {
                float v = red[tid] + red[128 + tid];
                int s = tid >> 3, c = tid & 7;
                int g = base + s;
                if (c < 7 && g < B) {
                    if (c == 0) v += __ldg(&bout[0]);
                    out[g * 7 + c] = v;
                }
            }
        }
        // (l<2: next layer's kc==0 __syncthreads orders epilogue stores before A reads)
    }
}

extern "C" void kernel_launch(void* const* d_in, const int* in_sizes, int n_in,
                              void* d_out, int out_size)
{
    const float* x    = (const float*)d_in[0];
    const float* W0   = (const float*)d_in[1];
    const float* b0   = (const float*)d_in[2];
    const float* W1   = (const float*)d_in[3];
    const float* b1   = (const float*)d_in[4];
    const float* W2   = (const float*)d_in[5];
    const float* b2   = (const float*)d_in[6];
    const float* W3   = (const float*)d_in[7];
    const float* b3   = (const float*)d_in[8];
    const float* Wout = (const float*)d_in[9];
    const float* bout = (const float*)d_in[10];
    float* out = (float*)d_out;

    const int B = in_sizes[0] / 3;
    const int nblk = (B + SPB - 1) / SPB;

    prep_w_kernel<<<(3 * HID * HID + 255) / 256, 256>>>(W1, W2, W3);

    cudaFuncSetAttribute(pinn_mma_kernel,
                         cudaFuncAttributeMaxDynamicSharedMemorySize, SMEM_TOTAL);
    pinn_mma_kernel<<<nblk, TPB, SMEM_TOTAL>>>(x, W0, b0, b1, b2, b3,
                                               Wout, bout, out, B);
}

// round 6
// speedup vs baseline: 1.7556x; 1.0598x over previous
#include <cuda_runtime.h>
#include <cuda_bf16.h>
#include <cstdint>
#include <math.h>

#define HID 256
#define SPB 16          // samples per block -> M = 128 jet rows
#define TPB 512         // 16 warps: 4 m32-tiles x 4 n64-tiles

#define RSA 528         // A smem row stride bytes (264 bf16: 256 + 8 pad)
#define RSW 80          // W chunk smem row stride bytes (40 bf16: 32 + 8 pad)

// ---- dynamic smem offsets (bytes) ----
#define SM_RED   0                          // 4 slices x 128 floats = 2048
#define SM_AH    2048
#define SM_AL    (SM_AH + 128 * RSA)        // +67584
#define SM_W     (SM_AL + 128 * RSA)        // 137216
#define WBUF_SZ  (2 * 256 * RSW)            // 40960 (hi + lo planes)
#define SMEM_TOTAL (SM_W + 2 * WBUF_SZ)     // 219136

// pre-transposed hi/lo weights: g_wt[layer][part][n*256 + k]  (WT[n][k] = W[k][n])
__device__ __align__(16) __nv_bfloat16 g_wt[3][2][HID * HID];

// ---------------- helpers ----------------
__device__ __forceinline__ uint32_t smem_u32(const void* p) {
    uint32_t a;
    asm("{ .reg .u64 t; cvta.to.shared.u64 t, %1; cvt.u32.u64 %0, t; }" : "=r"(a) : "l"(p));
    return a;
}
__device__ __forceinline__ void ldsm_x4(uint32_t addr, uint32_t r[4]) {
    asm volatile("ldmatrix.sync.aligned.m8n8.x4.shared.b16 {%0,%1,%2,%3}, [%4];"
                 : "=r"(r[0]), "=r"(r[1]), "=r"(r[2]), "=r"(r[3]) : "r"(addr));
}
__device__ __forceinline__ void mma16816(float d[4], const uint32_t a[4],
                                         uint32_t b0, uint32_t b1) {
    asm volatile("mma.sync.aligned.m16n8k16.row.col.f32.bf16.bf16.f32 "
                 "{%0,%1,%2,%3},{%4,%5,%6,%7},{%8,%9},{%0,%1,%2,%3};"
                 : "+f"(d[0]), "+f"(d[1]), "+f"(d[2]), "+f"(d[3])
                 : "r"(a[0]), "r"(a[1]), "r"(a[2]), "r"(a[3]), "r"(b0), "r"(b1));
}
__device__ __forceinline__ void cp16(uint32_t dst, const void* src) {
    asm volatile("cp.async.ca.shared.global [%0], [%1], 16;" :: "r"(dst), "l"(src));
}
#define CP_COMMIT() asm volatile("cp.async.commit_group;" ::: "memory")
#define CP_WAIT0()  asm volatile("cp.async.wait_group 0;" ::: "memory")

__device__ __forceinline__ float my_tanhf(float z) {
    float a = fabsf(z);
    float e = __expf(-2.0f * a);
    float t = __fdividef(1.0f - e, 1.0f + e);
    return copysignf(t, z);
}
__device__ __forceinline__ void split_pack(float a, float b, uint32_t& hi, uint32_t& lo) {
    __nv_bfloat16 ha = __float2bfloat16(a), hb = __float2bfloat16(b);
    __nv_bfloat16 la = __float2bfloat16(a - __bfloat162float(ha));
    __nv_bfloat16 lb = __float2bfloat16(b - __bfloat162float(hb));
    hi = (uint32_t)__bfloat16_as_ushort(ha) | ((uint32_t)__bfloat16_as_ushort(hb) << 16);
    lo = (uint32_t)__bfloat16_as_ushort(la) | ((uint32_t)__bfloat16_as_ushort(lb) << 16);
}
__device__ __forceinline__ void storeA(char* smem, int m, int nc, float v0, float v1) {
    uint32_t hi, lo; split_pack(v0, v1, hi, lo);
    int off = m * RSA + nc * 2;
    *(uint32_t*)(smem + SM_AH + off) = hi;
    *(uint32_t*)(smem + SM_AL + off) = lo;
}

// ---------------- prep: W[k][n] -> WT[n][k] bf16 hi/lo ----------------
__global__ void prep_w_kernel(const float* __restrict__ W1, const float* __restrict__ W2,
                              const float* __restrict__ W3) {
    int idx = blockIdx.x * blockDim.x + threadIdx.x;
    if (idx >= 3 * HID * HID) return;
    int l = idx >> 16, r = idx & 65535;
    int k = r >> 8, n = r & 255;
    const float* W = (l == 0) ? W1 : (l == 1) ? W2 : W3;
    float v = W[k * HID + n];
    __nv_bfloat16 h = __float2bfloat16(v);
    __nv_bfloat16 lo = __float2bfloat16(v - __bfloat162float(h));
    g_wt[l][0][n * HID + k] = h;
    g_wt[l][1][n * HID + k] = lo;
}

// ---------------- main kernel ----------------
__global__ __launch_bounds__(TPB, 1) void pinn_mma_kernel(
    const float* __restrict__ x,
    const float* __restrict__ W0, const float* __restrict__ b0,
    const float* __restrict__ b1, const float* __restrict__ b2,
    const float* __restrict__ b3,
    const float* __restrict__ Wout, const float* __restrict__ bout,
    float* __restrict__ out, int B)
{
    extern __shared__ char smem[];
    const uint32_t sb = smem_u32(smem);
    const int tid = threadIdx.x, wid = tid >> 5, lane = tid & 31;
    const int base = blockIdx.x * SPB;

    // -------- layer 0: analytic jets -> A (rows m = s*8 + ch) --------
    {
        const int nc = (tid & 127) * 2;
        const int sg = tid >> 7;
        float wa0 = __ldg(&W0[nc]),     wa1 = __ldg(&W0[HID + nc]),     wa2 = __ldg(&W0[2*HID + nc]);
        float wb0 = __ldg(&W0[nc + 1]), wb1 = __ldg(&W0[HID + nc + 1]), wb2 = __ldg(&W0[2*HID + nc + 1]);
        float ba = __ldg(&b0[nc]), bb = __ldg(&b0[nc + 1]);
        #pragma unroll
        for (int i = 0; i < 4; i++) {
            int s = sg * 4 + i;
            int idx = base + s; if (idx >= B) idx = B - 1;
            float x0 = __ldg(&x[idx*3]), x1 = __ldg(&x[idx*3+1]), x2 = __ldg(&x[idx*3+2]);
            float za = fmaf(x2, wa2, fmaf(x1, wa1, fmaf(x0, wa0, ba)));
            float zb = fmaf(x2, wb2, fmaf(x1, wb1, fmaf(x0, wb0, bb)));
            float hA = my_tanhf(za), tA = 1.f - hA*hA, cA = -2.f*hA*tA;
            float hB = my_tanhf(zb), tB = 1.f - hB*hB, cB = -2.f*hB*tB;
            float va[8] = {hA, tA*wa0, tA*wa1, tA*wa2, cA*wa0*wa0, cA*wa1*wa1, cA*wa2*wa2, 0.f};
            float vb[8] = {hB, tB*wb0, tB*wb1, tB*wb2, cB*wb0*wb0, cB*wb1*wb1, cB*wb2*wb2, 0.f};
            #pragma unroll
            for (int c = 0; c < 8; c++) storeA(smem, s * 8 + c, nc, va[c], vb[c]);
        }
    }
    __syncthreads();

    // warp tiling: warp = m32 x n64  (mt = wid&3, ntq = wid>>2)
    const int mt  = wid & 3;
    const int ntq = wid >> 2;
    const int mrow0 = mt * 32;
    const int ncol0 = ntq * 64;
    const int ch = lane >> 2;               // channel 0..7
    const int srcb = lane & 3;
    // A frag lane addr (per m16 tile t: + t*16*RSA)
    const uint32_t aOff = (uint32_t)((mrow0 + (lane & 15)) * RSA + (lane >> 4) * 16);
    // B frag lane addr within an n16 x k16 block
    const uint32_t bOff = (uint32_t)((((lane & 7) + ((lane >> 4) << 3)) * RSW)
                                     + ((lane >> 3) & 1) * 16);

    #pragma unroll 1
    for (int l = 0; l < 3; l++) {
        float acc[2][8][4];
        #pragma unroll
        for (int t = 0; t < 2; t++)
            #pragma unroll
            for (int nt = 0; nt < 8; nt++)
                { acc[t][nt][0]=0.f; acc[t][nt][1]=0.f; acc[t][nt][2]=0.f; acc[t][nt][3]=0.f; }

        #pragma unroll 1
        for (int kc = 0; kc < 8; kc++) {
            if (kc == 0) {
                #pragma unroll
                for (int i = 0; i < 4; i++) {
                    int idx = tid + i * 512;
                    int seg = idx & 3, n = (idx >> 2) & 255, part = idx >> 10;
                    const char* src = (const char*)&g_wt[l][part][n * HID] + seg * 16;
                    cp16(sb + SM_W + part * 20480 + (uint32_t)(n * RSW + seg * 16), src);
                }
                CP_COMMIT(); CP_WAIT0();
                __syncthreads();
            }
            if (kc < 7) {
                uint32_t wdst = sb + SM_W + (uint32_t)(((kc + 1) & 1) * WBUF_SZ);
                #pragma unroll
                for (int i = 0; i < 4; i++) {
                    int idx = tid + i * 512;
                    int seg = idx & 3, n = (idx >> 2) & 255, part = idx >> 10;
                    const char* src = (const char*)&g_wt[l][part][n * HID + (kc + 1) * 32] + seg * 16;
                    cp16(wdst + part * 20480 + (uint32_t)(n * RSW + seg * 16), src);
                }
                CP_COMMIT();
            }
            const uint32_t wb = sb + SM_W + (uint32_t)((kc & 1) * WBUF_SZ);
            #pragma unroll
            for (int ks = 0; ks < 2; ks++) {
                const uint32_t akb = (uint32_t)(kc * 64 + ks * 32);
                uint32_t ah[2][4], al[2][4];
                #pragma unroll
                for (int t = 0; t < 2; t++) {
                    ldsm_x4(sb + SM_AH + aOff + (uint32_t)(t * 16 * RSA) + akb, ah[t]);
                    ldsm_x4(sb + SM_AL + aOff + (uint32_t)(t * 16 * RSA) + akb, al[t]);
                }
                #pragma unroll
                for (int p = 0; p < 4; p++) {
                    uint32_t bh[4], bl[4];
                    uint32_t wrow = wb + (uint32_t)((ncol0 + p * 16) * RSW) + bOff
                                  + (uint32_t)(ks * 32);
                    ldsm_x4(wrow, bh);
                    ldsm_x4(wrow + 20480, bl);
                    #pragma unroll
                    for (int t = 0; t < 2; t++) {
                        mma16816(acc[t][2*p],   ah[t], bh[0], bh[1]);
                        mma16816(acc[t][2*p],   al[t], bh[0], bh[1]);
                        mma16816(acc[t][2*p],   ah[t], bl[0], bl[1]);
                        mma16816(acc[t][2*p+1], ah[t], bh[2], bh[3]);
                        mma16816(acc[t][2*p+1], al[t], bh[2], bh[3]);
                        mma16816(acc[t][2*p+1], ah[t], bl[2], bl[3]);
                    }
                }
            }
            if (kc < 7) { CP_WAIT0(); __syncthreads(); }
        }
        __syncthreads();   // all MMA reads of A done before epilogue overwrites A

        // -------- epilogue: z-jets -> activation jets --------
        const float* bp = (l == 0) ? b1 : (l == 1) ? b2 : b3;
        float accO[2][2] = {{0.f, 0.f}, {0.f, 0.f}};
        const int gsrc = (lane - 12) & 31;

        #pragma unroll
        for (int t = 0; t < 2; t++) {
            #pragma unroll
            for (int nt = 0; nt < 8; nt++) {
                int ncol = ncol0 + nt * 8 + (srcb << 1);
                float z0 = acc[t][nt][0], z1 = acc[t][nt][1];
                float z2 = acc[t][nt][2], z3 = acc[t][nt][3];
                float bi0 = __ldg(&bp[ncol]), bi1 = __ldg(&bp[ncol + 1]);
                float zb0 = __shfl_sync(0xffffffffu, z0, srcb) + bi0;
                float zb1 = __shfl_sync(0xffffffffu, z1, srcb) + bi1;
                float zb2 = __shfl_sync(0xffffffffu, z2, srcb) + bi0;
                float zb3 = __shfl_sync(0xffffffffu, z3, srcb) + bi1;
                float h0 = my_tanhf(zb0), t0 = 1.f - h0*h0, c0 = -2.f*h0*t0;
                float h1 = my_tanhf(zb1), t1 = 1.f - h1*h1, c1 = -2.f*h1*t1;
                float h2 = my_tanhf(zb2), t2 = 1.f - h2*h2, c2 = -2.f*h2*t2;
                float h3 = my_tanhf(zb3), t3 = 1.f - h3*h3, c3 = -2.f*h3*t3;
                float zg0 = __shfl_sync(0xffffffffu, z0, gsrc);
                float zg1 = __shfl_sync(0xffffffffu, z1, gsrc);
                float zg2 = __shfl_sync(0xffffffffu, z2, gsrc);
                float zg3 = __shfl_sync(0xffffffffu, z3, gsrc);
                float o0 = (ch == 0) ? h0 : (ch < 4) ? t0 * z0
                         : (ch < 7) ? fmaf(c0 * zg0, zg0, t0 * z0) : 0.f;
                float o1 = (ch == 0) ? h1 : (ch < 4) ? t1 * z1
                         : (ch < 7) ? fmaf(c1 * zg1, zg1, t1 * z1) : 0.f;
                float o2 = (ch == 0) ? h2 : (ch < 4) ? t2 * z2
                         : (ch < 7) ? fmaf(c2 * zg2, zg2, t2 * z2) : 0.f;
                float o3 = (ch == 0) ? h3 : (ch < 4) ? t3 * z3
                         : (ch < 7) ? fmaf(c3 * zg3, zg3, t3 * z3) : 0.f;
                if (l < 2) {
                    storeA(smem, mrow0 + t * 16 + ch,     ncol, o0, o1);
                    storeA(smem, mrow0 + t * 16 + ch + 8, ncol, o2, o3);
                } else {
                    float w0 = __ldg(&Wout[ncol]), w1 = __ldg(&Wout[ncol + 1]);
                    accO[t][0] = fmaf(o0, w0, fmaf(o1, w1, accO[t][0]));
                    accO[t][1] = fmaf(o2, w0, fmaf(o3, w1, accO[t][1]));
                }
            }
        }

        if (l == 2) {
            #pragma unroll
            for (int t = 0; t < 2; t++) {
                accO[t][0] += __shfl_xor_sync(0xffffffffu, accO[t][0], 1);
                accO[t][0] += __shfl_xor_sync(0xffffffffu, accO[t][0], 2);
                accO[t][1] += __shfl_xor_sync(0xffffffffu, accO[t][1], 1);
                accO[t][1] += __shfl_xor_sync(0xffffffffu, accO[t][1], 2);
            }
            float* red = (float*)(smem + SM_RED);
            if (srcb == 0) {
                #pragma unroll
                for (int t = 0; t < 2; t++) {
                    red[ntq * 128 + mrow0 + t * 16 + ch]     = accO[t][0];
                    red[ntq * 128 + mrow0 + t * 16 + ch + 8] = accO[t][1];
                }
            }
            __syncthreads();
            if (tid < 128) {
                float v = red[tid] + red[128 + tid] + red[256 + tid] + red[384 + tid];
                int s = tid >> 3, c = tid & 7;
                int g = base + s;
                if (c < 7 && g < B) {
                    if (c == 0) v += __ldg(&bout[0]);
                    out[g * 7 + c] = v;
                }
            }
        }
    }
}

extern "C" void kernel_launch(void* const* d_in, const int* in_sizes, int n_in,
                              void* d_out, int out_size)
{
    const float* x    = (const float*)d_in[0];
    const float* W0   = (const float*)d_in[1];
    const float* b0   = (const float*)d_in[2];
    const float* W1   = (const float*)d_in[3];
    const float* b1   = (const float*)d_in[4];
    const float* W2   = (const float*)d_in[5];
    const float* b2   = (const float*)d_in[6];
    const float* W3   = (const float*)d_in[7];
    const float* b3   = (const float*)d_in[8];
    const float* Wout = (const float*)d_in[9];
    const float* bout = (const float*)d_in[10];
    float* out = (float*)d_out;

    const int B = in_sizes[0] / 3;
    const int nblk = (B + SPB - 1) / SPB;

    prep_w_kernel<<<(3 * HID * HID + 255) / 256, 256>>>(W1, W2, W3);

    cudaFuncSetAttribute(pinn_mma_kernel,
                         cudaFuncAttributeMaxDynamicSharedMemorySize, SMEM_TOTAL);
    pinn_mma_kernel<<<nblk, TPB, SMEM_TOTAL>>>(x, W0, b0, b1, b2, b3,
                                               Wout, bout, out, B);
}

// round 7
// speedup vs baseline: 1.8113x; 1.0317x over previous
#include <cuda_runtime.h>
#include <cuda_bf16.h>
#include <cstdint>
#include <math.h>

#define HID 256
#define SPB 8           // samples per block -> M = 64 jet rows
#define TPB 256         // 8 warps: 2 m32-tiles x 4 n64-tiles

#define RSA 528         // A smem row stride bytes (264 bf16: 256 + 8 pad)
#define RSW 80          // W chunk smem row stride bytes (40 bf16: 32 + 8 pad)

// ---- dynamic smem offsets (bytes) ----
#define SM_RED   0                          // 4 slices x 64 floats = 1024
#define SM_AH    1024
#define SM_AL    (SM_AH + 64 * RSA)         // 34816
#define SM_W     (SM_AL + 64 * RSA)         // 68608  (single buffer, hi+lo planes)
#define WBUF_SZ  (2 * 256 * RSW)            // 40960
#define SMEM_TOTAL (SM_W + WBUF_SZ)         // 109568  -> 2 blocks/SM

// pre-transposed hi/lo weights: g_wt[layer][part][n*256 + k]  (WT[n][k] = W[k][n])
__device__ __align__(16) __nv_bfloat16 g_wt[3][2][HID * HID];

// ---------------- helpers ----------------
__device__ __forceinline__ uint32_t smem_u32(const void* p) {
    uint32_t a;
    asm("{ .reg .u64 t; cvta.to.shared.u64 t, %1; cvt.u32.u64 %0, t; }" : "=r"(a) : "l"(p));
    return a;
}
__device__ __forceinline__ void ldsm_x4(uint32_t addr, uint32_t r[4]) {
    asm volatile("ldmatrix.sync.aligned.m8n8.x4.shared.b16 {%0,%1,%2,%3}, [%4];"
                 : "=r"(r[0]), "=r"(r[1]), "=r"(r[2]), "=r"(r[3]) : "r"(addr));
}
__device__ __forceinline__ void mma16816(float d[4], const uint32_t a[4],
                                         uint32_t b0, uint32_t b1) {
    asm volatile("mma.sync.aligned.m16n8k16.row.col.f32.bf16.bf16.f32 "
                 "{%0,%1,%2,%3},{%4,%5,%6,%7},{%8,%9},{%0,%1,%2,%3};"
                 : "+f"(d[0]), "+f"(d[1]), "+f"(d[2]), "+f"(d[3])
                 : "r"(a[0]), "r"(a[1]), "r"(a[2]), "r"(a[3]), "r"(b0), "r"(b1));
}
__device__ __forceinline__ void cp16(uint32_t dst, const void* src) {
    asm volatile("cp.async.ca.shared.global [%0], [%1], 16;" :: "r"(dst), "l"(src));
}
#define CP_COMMIT() asm volatile("cp.async.commit_group;" ::: "memory")
#define CP_WAIT0()  asm volatile("cp.async.wait_group 0;" ::: "memory")

__device__ __forceinline__ float my_tanhf(float z) {
    float a = fabsf(z);
    float e = __expf(-2.0f * a);
    float t = __fdividef(1.0f - e, 1.0f + e);
    return copysignf(t, z);
}
__device__ __forceinline__ void split_pack(float a, float b, uint32_t& hi, uint32_t& lo) {
    __nv_bfloat16 ha = __float2bfloat16(a), hb = __float2bfloat16(b);
    __nv_bfloat16 la = __float2bfloat16(a - __bfloat162float(ha));
    __nv_bfloat16 lb = __float2bfloat16(b - __bfloat162float(hb));
    hi = (uint32_t)__bfloat16_as_ushort(ha) | ((uint32_t)__bfloat16_as_ushort(hb) << 16);
    lo = (uint32_t)__bfloat16_as_ushort(la) | ((uint32_t)__bfloat16_as_ushort(lb) << 16);
}
__device__ __forceinline__ void storeA(char* smem, int m, int nc, float v0, float v1) {
    uint32_t hi, lo; split_pack(v0, v1, hi, lo);
    int off = m * RSA + nc * 2;
    *(uint32_t*)(smem + SM_AH + off) = hi;
    *(uint32_t*)(smem + SM_AL + off) = lo;
}

// ---------------- prep: W[k][n] -> WT[n][k] bf16 hi/lo ----------------
__global__ void prep_w_kernel(const float* __restrict__ W1, const float* __restrict__ W2,
                              const float* __restrict__ W3) {
    int idx = blockIdx.x * blockDim.x + threadIdx.x;
    if (idx >= 3 * HID * HID) return;
    int l = idx >> 16, r = idx & 65535;
    int k = r >> 8, n = r & 255;
    const float* W = (l == 0) ? W1 : (l == 1) ? W2 : W3;
    float v = W[k * HID + n];
    __nv_bfloat16 h = __float2bfloat16(v);
    __nv_bfloat16 lo = __float2bfloat16(v - __bfloat162float(h));
    g_wt[l][0][n * HID + k] = h;
    g_wt[l][1][n * HID + k] = lo;
}

// ---------------- main kernel ----------------
__global__ __launch_bounds__(TPB, 2) void pinn_mma_kernel(
    const float* __restrict__ x,
    const float* __restrict__ W0, const float* __restrict__ b0,
    const float* __restrict__ b1, const float* __restrict__ b2,
    const float* __restrict__ b3,
    const float* __restrict__ Wout, const float* __restrict__ bout,
    float* __restrict__ out, int B)
{
    extern __shared__ char smem[];
    const uint32_t sb = smem_u32(smem);
    const int tid = threadIdx.x, wid = tid >> 5, lane = tid & 31;
    const int base = blockIdx.x * SPB;

    // -------- layer 0: analytic jets -> A (rows m = s*8 + ch) --------
    {
        const int nc = (tid & 127) * 2;
        const int sg = tid >> 7;                 // 2 groups x 4 samples
        float wa0 = __ldg(&W0[nc]),     wa1 = __ldg(&W0[HID + nc]),     wa2 = __ldg(&W0[2*HID + nc]);
        float wb0 = __ldg(&W0[nc + 1]), wb1 = __ldg(&W0[HID + nc + 1]), wb2 = __ldg(&W0[2*HID + nc + 1]);
        float ba = __ldg(&b0[nc]), bb = __ldg(&b0[nc + 1]);
        #pragma unroll
        for (int i = 0; i < 4; i++) {
            int s = sg * 4 + i;
            int idx = base + s; if (idx >= B) idx = B - 1;
            float x0 = __ldg(&x[idx*3]), x1 = __ldg(&x[idx*3+1]), x2 = __ldg(&x[idx*3+2]);
            float za = fmaf(x2, wa2, fmaf(x1, wa1, fmaf(x0, wa0, ba)));
            float zb = fmaf(x2, wb2, fmaf(x1, wb1, fmaf(x0, wb0, bb)));
            float hA = my_tanhf(za), tA = 1.f - hA*hA, cA = -2.f*hA*tA;
            float hB = my_tanhf(zb), tB = 1.f - hB*hB, cB = -2.f*hB*tB;
            float va[8] = {hA, tA*wa0, tA*wa1, tA*wa2, cA*wa0*wa0, cA*wa1*wa1, cA*wa2*wa2, 0.f};
            float vb[8] = {hB, tB*wb0, tB*wb1, tB*wb2, cB*wb0*wb0, cB*wb1*wb1, cB*wb2*wb2, 0.f};
            #pragma unroll
            for (int c = 0; c < 8; c++) storeA(smem, s * 8 + c, nc, va[c], vb[c]);
        }
    }

    // warp tiling: warp = m32 x n64  (mt = wid&1, ntq = wid>>1)
    const int mt  = wid & 1;
    const int ntq = wid >> 1;
    const int mrow0 = mt * 32;
    const int ncol0 = ntq * 64;
    const int ch = lane >> 2;               // channel 0..7
    const int srcb = lane & 3;
    const uint32_t aOff = (uint32_t)((mrow0 + (lane & 15)) * RSA + (lane >> 4) * 16);
    const uint32_t bOff = (uint32_t)((((lane & 7) + ((lane >> 4) << 3)) * RSW)
                                     + ((lane >> 3) & 1) * 16);

    #pragma unroll 1
    for (int l = 0; l < 3; l++) {
        float acc[2][8][4];
        #pragma unroll
        for (int t = 0; t < 2; t++)
            #pragma unroll
            for (int nt = 0; nt < 8; nt++)
                { acc[t][nt][0]=0.f; acc[t][nt][1]=0.f; acc[t][nt][2]=0.f; acc[t][nt][3]=0.f; }

        #pragma unroll 1
        for (int kc = 0; kc < 8; kc++) {
            __syncthreads();   // prior chunk's MMA reads done / (kc==0) A writes visible
            // load W chunk kc (single buffer): 2 planes x 256 rows x 64B
            #pragma unroll
            for (int i = 0; i < 8; i++) {
                int idx = tid + i * 256;
                int seg = idx & 3, n = (idx >> 2) & 255, part = idx >> 10;
                const char* src = (const char*)&g_wt[l][part][n * HID + kc * 32] + seg * 16;
                cp16(sb + SM_W + part * 20480 + (uint32_t)(n * RSW + seg * 16), src);
            }
            CP_COMMIT(); CP_WAIT0();
            __syncthreads();

            #pragma unroll
            for (int ks = 0; ks < 2; ks++) {
                const uint32_t akb = (uint32_t)(kc * 64 + ks * 32);
                uint32_t ah[2][4], al[2][4];
                #pragma unroll
                for (int t = 0; t < 2; t++) {
                    ldsm_x4(sb + SM_AH + aOff + (uint32_t)(t * 16 * RSA) + akb, ah[t]);
                    ldsm_x4(sb + SM_AL + aOff + (uint32_t)(t * 16 * RSA) + akb, al[t]);
                }
                #pragma unroll
                for (int p = 0; p < 4; p++) {
                    uint32_t bh[4], bl[4];
                    uint32_t wrow = sb + SM_W + (uint32_t)((ncol0 + p * 16) * RSW) + bOff
                                  + (uint32_t)(ks * 32);
                    ldsm_x4(wrow, bh);
                    ldsm_x4(wrow + 20480, bl);
                    #pragma unroll
                    for (int t = 0; t < 2; t++) {
                        mma16816(acc[t][2*p],   ah[t], bh[0], bh[1]);
                        mma16816(acc[t][2*p],   al[t], bh[0], bh[1]);
                        mma16816(acc[t][2*p],   ah[t], bl[0], bl[1]);
                        mma16816(acc[t][2*p+1], ah[t], bh[2], bh[3]);
                        mma16816(acc[t][2*p+1], al[t], bh[2], bh[3]);
                        mma16816(acc[t][2*p+1], ah[t], bl[2], bl[3]);
                    }
                }
            }
        }
        __syncthreads();   // all MMA reads of A done before epilogue overwrites A

        // -------- epilogue: z-jets -> activation jets --------
        const float* bp = (l == 0) ? b1 : (l == 1) ? b2 : b3;
        float accO[2][2] = {{0.f, 0.f}, {0.f, 0.f}};
        const int gsrc = (lane - 12) & 31;

        #pragma unroll
        for (int t = 0; t < 2; t++) {
            #pragma unroll
            for (int nt = 0; nt < 8; nt++) {
                int ncol = ncol0 + nt * 8 + (srcb << 1);
                float z0 = acc[t][nt][0], z1 = acc[t][nt][1];
                float z2 = acc[t][nt][2], z3 = acc[t][nt][3];
                float bi0 = __ldg(&bp[ncol]), bi1 = __ldg(&bp[ncol + 1]);
                float zb0 = __shfl_sync(0xffffffffu, z0, srcb) + bi0;
                float zb1 = __shfl_sync(0xffffffffu, z1, srcb) + bi1;
                float zb2 = __shfl_sync(0xffffffffu, z2, srcb) + bi0;
                float zb3 = __shfl_sync(0xffffffffu, z3, srcb) + bi1;
                float h0 = my_tanhf(zb0), t0 = 1.f - h0*h0, c0 = -2.f*h0*t0;
                float h1 = my_tanhf(zb1), t1 = 1.f - h1*h1, c1 = -2.f*h1*t1;
                float h2 = my_tanhf(zb2), t2 = 1.f - h2*h2, c2 = -2.f*h2*t2;
                float h3 = my_tanhf(zb3), t3 = 1.f - h3*h3, c3 = -2.f*h3*t3;
                float zg0 = __shfl_sync(0xffffffffu, z0, gsrc);
                float zg1 = __shfl_sync(0xffffffffu, z1, gsrc);
                float zg2 = __shfl_sync(0xffffffffu, z2, gsrc);
                float zg3 = __shfl_sync(0xffffffffu, z3, gsrc);
                float o0 = (ch == 0) ? h0 : (ch < 4) ? t0 * z0
                         : (ch < 7) ? fmaf(c0 * zg0, zg0, t0 * z0) : 0.f;
                float o1 = (ch == 0) ? h1 : (ch < 4) ? t1 * z1
                         : (ch < 7) ? fmaf(c1 * zg1, zg1, t1 * z1) : 0.f;
                float o2 = (ch == 0) ? h2 : (ch < 4) ? t2 * z2
                         : (ch < 7) ? fmaf(c2 * zg2, zg2, t2 * z2) : 0.f;
                float o3 = (ch == 0) ? h3 : (ch < 4) ? t3 * z3
                         : (ch < 7) ? fmaf(c3 * zg3, zg3, t3 * z3) : 0.f;
                if (l < 2) {
                    storeA(smem, mrow0 + t * 16 + ch,     ncol, o0, o1);
                    storeA(smem, mrow0 + t * 16 + ch + 8, ncol, o2, o3);
                } else {
                    float w0 = __ldg(&Wout[ncol]), w1 = __ldg(&Wout[ncol + 1]);
                    accO[t][0] = fmaf(o0, w0, fmaf(o1, w1, accO[t][0]));
                    accO[t][1] = fmaf(o2, w0, fmaf(o3, w1, accO[t][1]));
                }
            }
        }

        if (l == 2) {
            #pragma unroll
            for (int t = 0; t < 2; t++) {
                accO[t][0] += __shfl_xor_sync(0xffffffffu, accO[t][0], 1);
                accO[t][0] += __shfl_xor_sync(0xffffffffu, accO[t][0], 2);
                accO[t][1] += __shfl_xor_sync(0xffffffffu, accO[t][1], 1);
                accO[t][1] += __shfl_xor_sync(0xffffffffu, accO[t][1], 2);
            }
            float* red = (float*)(smem + SM_RED);
            if (srcb == 0) {
                #pragma unroll
                for (int t = 0; t < 2; t++) {
                    red[ntq * 64 + mrow0 + t * 16 + ch]     = accO[t][0];
                    red[ntq * 64 + mrow0 + t * 16 + ch + 8] = accO[t][1];
                }
            }
            __syncthreads();
            if (tid < 64) {
                float v = red[tid] + red[64 + tid] + red[128 + tid] + red[192 + tid];
                int s = tid >> 3, c = tid & 7;
                int g = base + s;
                if (c < 7 && g < B) {
                    if (c == 0) v += __ldg(&bout[0]);
                    out[g * 7 + c] = v;
                }
            }
        }
    }
}

extern "C" void kernel_launch(void* const* d_in, const int* in_sizes, int n_in,
                              void* d_out, int out_size)
{
    const float* x    = (const float*)d_in[0];
    const float* W0   = (const float*)d_in[1];
    const float* b0   = (const float*)d_in[2];
    const float* W1   = (const float*)d_in[3];
    const float* b1   = (const float*)d_in[4];
    const float* W2   = (const float*)d_in[5];
    const float* b2   = (const float*)d_in[6];
    const float* W3   = (const float*)d_in[7];
    const float* b3   = (const float*)d_in[8];
    const float* Wout = (const float*)d_in[9];
    const float* bout = (const float*)d_in[10];
    float* out = (float*)d_out;

    const int B = in_sizes[0] / 3;
    const int nblk = (B + SPB - 1) / SPB;

    prep_w_kernel<<<(3 * HID * HID + 255) / 256, 256>>>(W1, W2, W3);

    cudaFuncSetAttribute(pinn_mma_kernel,
                         cudaFuncAttributeMaxDynamicSharedMemorySize, SMEM_TOTAL);
    pinn_mma_kernel<<<nblk, TPB, SMEM_TOTAL>>>(x, W0, b0, b1, b2, b3,
                                               Wout, bout, out, B);
}

// round 8
// speedup vs baseline: 2.5051x; 1.3831x over previous
#include <cuda_runtime.h>
#include <cuda_bf16.h>
#include <cstdint>
#include <math.h>

#define HID 256
#define SPB 8           // samples per block -> M = 64 jet rows
#define TPB 256         // 8 warps: 2 m32-tiles x 4 n64-tiles

#define RSA 528         // A smem row stride bytes (264 bf16: 256 + 8 pad)

// ---- dynamic smem offsets (bytes) ----
#define SM_RED   0
#define SM_AH    1024
#define SM_AL    (SM_AH + 64 * RSA)
#define SMEM_TOTAL (SM_AL + 64 * RSA)       // 68608 B -> 2 blocks/SM

// W pre-packed in exact m16n8k16 B-fragment layout:
// uint4 g_wfrag[(l*2+part)*4 + ntq][ki*4 + p][lane] ; block stride 2048 uint4
__device__ __align__(16) uint4 g_wfrag[3 * 2 * 4 * 2048];

// ---------------- helpers ----------------
__device__ __forceinline__ uint32_t smem_u32(const void* p) {
    uint32_t a;
    asm("{ .reg .u64 t; cvta.to.shared.u64 t, %1; cvt.u32.u64 %0, t; }" : "=r"(a) : "l"(p));
    return a;
}
__device__ __forceinline__ void ldsm_x4(uint32_t addr, uint32_t r[4]) {
    asm volatile("ldmatrix.sync.aligned.m8n8.x4.shared.b16 {%0,%1,%2,%3}, [%4];"
                 : "=r"(r[0]), "=r"(r[1]), "=r"(r[2]), "=r"(r[3]) : "r"(addr));
}
__device__ __forceinline__ void mma16816(float d[4], const uint32_t a[4],
                                         uint32_t b0, uint32_t b1) {
    asm volatile("mma.sync.aligned.m16n8k16.row.col.f32.bf16.bf16.f32 "
                 "{%0,%1,%2,%3},{%4,%5,%6,%7},{%8,%9},{%0,%1,%2,%3};"
                 : "+f"(d[0]), "+f"(d[1]), "+f"(d[2]), "+f"(d[3])
                 : "r"(a[0]), "r"(a[1]), "r"(a[2]), "r"(a[3]), "r"(b0), "r"(b1));
}
__device__ __forceinline__ float my_tanhf(float z) {
    float a = fabsf(z);
    float e = __expf(-2.0f * a);
    float t = __fdividef(1.0f - e, 1.0f + e);
    return copysignf(t, z);
}
__device__ __forceinline__ void split_pack(float a, float b, uint32_t& hi, uint32_t& lo) {
    __nv_bfloat16 ha = __float2bfloat16(a), hb = __float2bfloat16(b);
    __nv_bfloat16 la = __float2bfloat16(a - __bfloat162float(ha));
    __nv_bfloat16 lb = __float2bfloat16(b - __bfloat162float(hb));
    hi = (uint32_t)__bfloat16_as_ushort(ha) | ((uint32_t)__bfloat16_as_ushort(hb) << 16);
    lo = (uint32_t)__bfloat16_as_ushort(la) | ((uint32_t)__bfloat16_as_ushort(lb) << 16);
}
__device__ __forceinline__ void storeA(char* smem, int m, int nc, float v0, float v1) {
    uint32_t hi, lo; split_pack(v0, v1, hi, lo);
    int off = m * RSA + nc * 2;
    *(uint32_t*)(smem + SM_AH + off) = hi;
    *(uint32_t*)(smem + SM_AL + off) = lo;
}

// ---------------- prep: W -> B-fragment-layout hi/lo planes ----------------
// thread -> (l, nt16, ki, r, lane); writes one u32 per plane.
// B frag reg r: n = nt16*16 + 8*(r>>1) + lane/4 ; k = ki*16 + 8*(r&1) + 2*(lane%4)
__global__ void prep_w_kernel(const float* __restrict__ W1, const float* __restrict__ W2,
                              const float* __restrict__ W3) {
    int idx = blockIdx.x * blockDim.x + threadIdx.x;
    if (idx >= 3 * 32768) return;
    int l    = idx >> 15;
    int rem  = idx & 32767;
    int nt16 = rem >> 11;
    int ki   = (rem >> 7) & 15;
    int r    = (rem >> 5) & 3;
    int lane = rem & 31;
    int n = nt16 * 16 + ((r >> 1) << 3) + (lane >> 2);
    int k = ki * 16 + ((r & 1) << 3) + ((lane & 3) << 1);
    const float* W = (l == 0) ? W1 : (l == 1) ? W2 : W3;
    float v0 = W[k * HID + n];
    float v1 = W[(k + 1) * HID + n];
    __nv_bfloat16 h0 = __float2bfloat16(v0), h1 = __float2bfloat16(v1);
    __nv_bfloat16 l0 = __float2bfloat16(v0 - __bfloat162float(h0));
    __nv_bfloat16 l1 = __float2bfloat16(v1 - __bfloat162float(h1));
    uint32_t hip = (uint32_t)__bfloat16_as_ushort(h0) | ((uint32_t)__bfloat16_as_ushort(h1) << 16);
    uint32_t lop = (uint32_t)__bfloat16_as_ushort(l0) | ((uint32_t)__bfloat16_as_ushort(l1) << 16);
    int ntq = nt16 >> 2, p = nt16 & 3;
    int slot = ((ki * 4 + p) * 32 + lane) * 4 + r;
    uint32_t* w32 = (uint32_t*)g_wfrag;
    w32[(((l * 2 + 0) * 4 + ntq) * 2048) * 4 + slot] = hip;
    w32[(((l * 2 + 1) * 4 + ntq) * 2048) * 4 + slot] = lop;
}

// ---------------- main kernel ----------------
__global__ __launch_bounds__(TPB, 2) void pinn_mma_kernel(
    const float* __restrict__ x,
    const float* __restrict__ W0, const float* __restrict__ b0,
    const float* __restrict__ b1, const float* __restrict__ b2,
    const float* __restrict__ b3,
    const float* __restrict__ Wout, const float* __restrict__ bout,
    float* __restrict__ out, int B)
{
    extern __shared__ char smem[];
    const uint32_t sb = smem_u32(smem);
    const int tid = threadIdx.x, wid = tid >> 5, lane = tid & 31;
    const int base = blockIdx.x * SPB;

    // -------- layer 0: analytic jets -> A (rows m = s*8 + ch) --------
    {
        const int nc = (tid & 127) * 2;
        const int sg = tid >> 7;
        float wa0 = __ldg(&W0[nc]),     wa1 = __ldg(&W0[HID + nc]),     wa2 = __ldg(&W0[2*HID + nc]);
        float wb0 = __ldg(&W0[nc + 1]), wb1 = __ldg(&W0[HID + nc + 1]), wb2 = __ldg(&W0[2*HID + nc + 1]);
        float ba = __ldg(&b0[nc]), bb = __ldg(&b0[nc + 1]);
        #pragma unroll
        for (int i = 0; i < 4; i++) {
            int s = sg * 4 + i;
            int idx = base + s; if (idx >= B) idx = B - 1;
            float x0 = __ldg(&x[idx*3]), x1 = __ldg(&x[idx*3+1]), x2 = __ldg(&x[idx*3+2]);
            float za = fmaf(x2, wa2, fmaf(x1, wa1, fmaf(x0, wa0, ba)));
            float zb = fmaf(x2, wb2, fmaf(x1, wb1, fmaf(x0, wb0, bb)));
            float hA = my_tanhf(za), tA = 1.f - hA*hA, cA = -2.f*hA*tA;
            float hB = my_tanhf(zb), tB = 1.f - hB*hB, cB = -2.f*hB*tB;
            float va[8] = {hA, tA*wa0, tA*wa1, tA*wa2, cA*wa0*wa0, cA*wa1*wa1, cA*wa2*wa2, 0.f};
            float vb[8] = {hB, tB*wb0, tB*wb1, tB*wb2, cB*wb0*wb0, cB*wb1*wb1, cB*wb2*wb2, 0.f};
            #pragma unroll
            for (int c = 0; c < 8; c++) storeA(smem, s * 8 + c, nc, va[c], vb[c]);
        }
    }
    __syncthreads();

    // warp tiling: warp = m32 x n64  (mt = wid&1, ntq = wid>>1)
    const int mt  = wid & 1;
    const int ntq = wid >> 1;
    const int mrow0 = mt * 32;
    const int ncol0 = ntq * 64;
    const int ch = lane >> 2;
    const int srcb = lane & 3;
    const uint32_t aOff = (uint32_t)((mrow0 + (lane & 15)) * RSA + (lane >> 4) * 16);

    #pragma unroll 1
    for (int l = 0; l < 3; l++) {
        float acc[2][8][4];
        #pragma unroll
        for (int t = 0; t < 2; t++)
            #pragma unroll
            for (int nt = 0; nt < 8; nt++)
                { acc[t][nt][0]=0.f; acc[t][nt][1]=0.f; acc[t][nt][2]=0.f; acc[t][nt][3]=0.f; }

        const uint4* fH = g_wfrag + (uint32_t)((l * 2 + 0) * 4 + ntq) * 2048 + lane;
        const uint4* fL = fH + 4 * 2048;

        #pragma unroll 2
        for (int ki = 0; ki < 16; ki++) {
            // A fragments (k16) for both m16 tiles, hi and lo planes
            uint32_t ah[2][4], al[2][4];
            const uint32_t akb = (uint32_t)(ki * 32);
            #pragma unroll
            for (int t = 0; t < 2; t++) {
                ldsm_x4(sb + SM_AH + aOff + (uint32_t)(t * 16 * RSA) + akb, ah[t]);
                ldsm_x4(sb + SM_AL + aOff + (uint32_t)(t * 16 * RSA) + akb, al[t]);
            }
            // B fragments via coalesced LDG.128 (L2-resident, fragment layout)
            uint4 bh[4], bl[4];
            #pragma unroll
            for (int p = 0; p < 4; p++) {
                bh[p] = __ldg(fH + (ki * 4 + p) * 32);
                bl[p] = __ldg(fL + (ki * 4 + p) * 32);
            }
            // term-major: 16 independent accumulators between revisits
            #pragma unroll
            for (int p = 0; p < 4; p++)
                #pragma unroll
                for (int t = 0; t < 2; t++) {
                    mma16816(acc[t][2*p],   ah[t], bh[p].x, bh[p].y);
                    mma16816(acc[t][2*p+1], ah[t], bh[p].z, bh[p].w);
                }
            #pragma unroll
            for (int p = 0; p < 4; p++)
                #pragma unroll
                for (int t = 0; t < 2; t++) {
                    mma16816(acc[t][2*p],   al[t], bh[p].x, bh[p].y);
                    mma16816(acc[t][2*p+1], al[t], bh[p].z, bh[p].w);
                }
            #pragma unroll
            for (int p = 0; p < 4; p++)
                #pragma unroll
                for (int t = 0; t < 2; t++) {
                    mma16816(acc[t][2*p],   ah[t], bl[p].x, bl[p].y);
                    mma16816(acc[t][2*p+1], ah[t], bl[p].z, bl[p].w);
                }
        }
        __syncthreads();   // all MMA reads of A done before epilogue overwrites A

        // -------- epilogue: z-jets -> activation jets --------
        const float* bp = (l == 0) ? b1 : (l == 1) ? b2 : b3;
        float accO[2][2] = {{0.f, 0.f}, {0.f, 0.f}};
        const int gsrc = (lane - 12) & 31;

        #pragma unroll
        for (int t = 0; t < 2; t++) {
            #pragma unroll
            for (int nt = 0; nt < 8; nt++) {
                int ncol = ncol0 + nt * 8 + (srcb << 1);
                float z0 = acc[t][nt][0], z1 = acc[t][nt][1];
                float z2 = acc[t][nt][2], z3 = acc[t][nt][3];
                float bi0 = __ldg(&bp[ncol]), bi1 = __ldg(&bp[ncol + 1]);
                float zb0 = __shfl_sync(0xffffffffu, z0, srcb) + bi0;
                float zb1 = __shfl_sync(0xffffffffu, z1, srcb) + bi1;
                float zb2 = __shfl_sync(0xffffffffu, z2, srcb) + bi0;
                float zb3 = __shfl_sync(0xffffffffu, z3, srcb) + bi1;
                float h0 = my_tanhf(zb0), t0 = 1.f - h0*h0, c0 = -2.f*h0*t0;
                float h1 = my_tanhf(zb1), t1 = 1.f - h1*h1, c1 = -2.f*h1*t1;
                float h2 = my_tanhf(zb2), t2 = 1.f - h2*h2, c2 = -2.f*h2*t2;
                float h3 = my_tanhf(zb3), t3 = 1.f - h3*h3, c3 = -2.f*h3*t3;
                float zg0 = __shfl_sync(0xffffffffu, z0, gsrc);
                float zg1 = __shfl_sync(0xffffffffu, z1, gsrc);
                float zg2 = __shfl_sync(0xffffffffu, z2, gsrc);
                float zg3 = __shfl_sync(0xffffffffu, z3, gsrc);
                float o0 = (ch == 0) ? h0 : (ch < 4) ? t0 * z0
                         : (ch < 7) ? fmaf(c0 * zg0, zg0, t0 * z0) : 0.f;
                float o1 = (ch == 0) ? h1 : (ch < 4) ? t1 * z1
                         : (ch < 7) ? fmaf(c1 * zg1, zg1, t1 * z1) : 0.f;
                float o2 = (ch == 0) ? h2 : (ch < 4) ? t2 * z2
                         : (ch < 7) ? fmaf(c2 * zg2, zg2, t2 * z2) : 0.f;
                float o3 = (ch == 0) ? h3 : (ch < 4) ? t3 * z3
                         : (ch < 7) ? fmaf(c3 * zg3, zg3, t3 * z3) : 0.f;
                if (l < 2) {
                    storeA(smem, mrow0 + t * 16 + ch,     ncol, o0, o1);
                    storeA(smem, mrow0 + t * 16 + ch + 8, ncol, o2, o3);
                } else {
                    float w0 = __ldg(&Wout[ncol]), w1 = __ldg(&Wout[ncol + 1]);
                    accO[t][0] = fmaf(o0, w0, fmaf(o1, w1, accO[t][0]));
                    accO[t][1] = fmaf(o2, w0, fmaf(o3, w1, accO[t][1]));
                }
            }
        }

        if (l < 2) {
            __syncthreads();   // A stores visible before next layer's LDSM
        } else {
            #pragma unroll
            for (int t = 0; t < 2; t++) {
                accO[t][0] += __shfl_xor_sync(0xffffffffu, accO[t][0], 1);
                accO[t][0] += __shfl_xor_sync(0xffffffffu, accO[t][0], 2);
                accO[t][1] += __shfl_xor_sync(0xffffffffu, accO[t][1], 1);
                accO[t][1] += __shfl_xor_sync(0xffffffffu, accO[t][1], 2);
            }
            float* red = (float*)(smem + SM_RED);
            if (srcb == 0) {
                #pragma unroll
                for (int t = 0; t < 2; t++) {
                    red[ntq * 64 + mrow0 + t * 16 + ch]     = accO[t][0];
                    red[ntq * 64 + mrow0 + t * 16 + ch + 8] = accO[t][1];
                }
            }
            __syncthreads();
            if (tid < 64) {
                float v = red[tid] + red[64 + tid] + red[128 + tid] + red[192 + tid];
                int s = tid >> 3, c = tid & 7;
                int g = base + s;
                if (c < 7 && g < B) {
                    if (c == 0) v += __ldg(&bout[0]);
                    out[g * 7 + c] = v;
                }
            }
        }
    }
}

extern "C" void kernel_launch(void* const* d_in, const int* in_sizes, int n_in,
                              void* d_out, int out_size)
{
    const float* x    = (const float*)d_in[0];
    const float* W0   = (const float*)d_in[1];
    const float* b0   = (const float*)d_in[2];
    const float* W1   = (const float*)d_in[3];
    const float* b1   = (const float*)d_in[4];
    const float* W2   = (const float*)d_in[5];
    const float* b2   = (const float*)d_in[6];
    const float* W3   = (const float*)d_in[7];
    const float* b3   = (const float*)d_in[8];
    const float* Wout = (const float*)d_in[9];
    const float* bout = (const float*)d_in[10];
    float* out = (float*)d_out;

    const int B = in_sizes[0] / 3;
    const int nblk = (B + SPB - 1) / SPB;

    prep_w_kernel<<<(3 * 32768 + 255) / 256, 256>>>(W1, W2, W3);

    cudaFuncSetAttribute(pinn_mma_kernel,
                         cudaFuncAttributeMaxDynamicSharedMemorySize, SMEM_TOTAL);
    pinn_mma_kernel<<<nblk, TPB, SMEM_TOTAL>>>(x, W0, b0, b1, b2, b3,
                                               Wout, bout, out, B);
}

// round 9
// speedup vs baseline: 3.3837x; 1.3507x over previous
#include <cuda_runtime.h>
#include <cuda_fp16.h>
#include <cstdint>
#include <math.h>

#define HID 256
#define SPB 8           // samples per block -> M = 64 jet rows
#define TPB 256         // 8 warps: 2 m32-tiles x 4 n64-tiles

#define RSA 528         // A smem row stride bytes (264 fp16: 256 + 8 pad)

// ---- dynamic smem offsets (bytes) ----
#define SM_RED   0
#define SM_AH    1024
#define SM_AL    (SM_AH + 64 * RSA)
#define SMEM_TOTAL (SM_AL + 64 * RSA)       // 68608 B -> 2 blocks/SM

// W (fp16, single plane) pre-packed in exact m16n8k16 B-fragment layout:
// uint4 g_wfrag[(l*4 + ntq)*2048 + (ki*4+p)*32 + lane]
__device__ __align__(16) uint4 g_wfrag[3 * 4 * 2048];

// ---------------- helpers ----------------
__device__ __forceinline__ uint32_t smem_u32(const void* p) {
    uint32_t a;
    asm("{ .reg .u64 t; cvta.to.shared.u64 t, %1; cvt.u32.u64 %0, t; }" : "=r"(a) : "l"(p));
    return a;
}
__device__ __forceinline__ void ldsm_x4(uint32_t addr, uint32_t r[4]) {
    asm volatile("ldmatrix.sync.aligned.m8n8.x4.shared.b16 {%0,%1,%2,%3}, [%4];"
                 : "=r"(r[0]), "=r"(r[1]), "=r"(r[2]), "=r"(r[3]) : "r"(addr));
}
__device__ __forceinline__ void mma16816(float d[4], const uint32_t a[4],
                                         uint32_t b0, uint32_t b1) {
    asm volatile("mma.sync.aligned.m16n8k16.row.col.f32.f16.f16.f32 "
                 "{%0,%1,%2,%3},{%4,%5,%6,%7},{%8,%9},{%0,%1,%2,%3};"
                 : "+f"(d[0]), "+f"(d[1]), "+f"(d[2]), "+f"(d[3])
                 : "r"(a[0]), "r"(a[1]), "r"(a[2]), "r"(a[3]), "r"(b0), "r"(b1));
}
__device__ __forceinline__ float my_tanhf(float z) {
    float a = fabsf(z);
    float e = __expf(-2.0f * a);
    float t = __fdividef(1.0f - e, 1.0f + e);
    return copysignf(t, z);
}
// fp16 hi/lo exact 2-way split of two floats, packed as {v0,v1} half2 words
__device__ __forceinline__ void split_pack(float a, float b, uint32_t& hi, uint32_t& lo) {
    __half ha = __float2half_rn(a), hb = __float2half_rn(b);
    __half la = __float2half_rn(a - __half2float(ha));
    __half lb = __float2half_rn(b - __half2float(hb));
    hi = (uint32_t)__half_as_ushort(ha) | ((uint32_t)__half_as_ushort(hb) << 16);
    lo = (uint32_t)__half_as_ushort(la) | ((uint32_t)__half_as_ushort(lb) << 16);
}
__device__ __forceinline__ void storeA(char* smem, int m, int nc, float v0, float v1) {
    uint32_t hi, lo; split_pack(v0, v1, hi, lo);
    int off = m * RSA + nc * 2;
    *(uint32_t*)(smem + SM_AH + off) = hi;
    *(uint32_t*)(smem + SM_AL + off) = lo;
}

// ---------------- prep: W -> fp16 B-fragment layout ----------------
// B frag reg r: n = nt16*16 + 8*(r>>1) + lane/4 ; k = ki*16 + 8*(r&1) + 2*(lane%4)
__global__ void prep_w_kernel(const float* __restrict__ W1, const float* __restrict__ W2,
                              const float* __restrict__ W3) {
    int idx = blockIdx.x * blockDim.x + threadIdx.x;
    if (idx >= 3 * 32768) return;
    int l    = idx >> 15;
    int rem  = idx & 32767;
    int nt16 = rem >> 11;
    int ki   = (rem >> 7) & 15;
    int r    = (rem >> 5) & 3;
    int lane = rem & 31;
    int n = nt16 * 16 + ((r >> 1) << 3) + (lane >> 2);
    int k = ki * 16 + ((r & 1) << 3) + ((lane & 3) << 1);
    const float* W = (l == 0) ? W1 : (l == 1) ? W2 : W3;
    float v0 = W[k * HID + n];
    float v1 = W[(k + 1) * HID + n];
    __half h0 = __float2half_rn(v0), h1 = __float2half_rn(v1);
    uint32_t hip = (uint32_t)__half_as_ushort(h0) | ((uint32_t)__half_as_ushort(h1) << 16);
    int ntq = nt16 >> 2, p = nt16 & 3;
    int slot = ((ki * 4 + p) * 32 + lane) * 4 + r;
    uint32_t* w32 = (uint32_t*)g_wfrag;
    w32[((l * 4 + ntq) * 2048) * 4 + slot] = hip;
}

// ---------------- main kernel ----------------
__global__ __launch_bounds__(TPB, 2) void pinn_mma_kernel(
    const float* __restrict__ x,
    const float* __restrict__ W0, const float* __restrict__ b0,
    const float* __restrict__ b1, const float* __restrict__ b2,
    const float* __restrict__ b3,
    const float* __restrict__ Wout, const float* __restrict__ bout,
    float* __restrict__ out, int B)
{
    extern __shared__ char smem[];
    const uint32_t sb = smem_u32(smem);
    const int tid = threadIdx.x, wid = tid >> 5, lane = tid & 31;
    const int base = blockIdx.x * SPB;

    // -------- layer 0: analytic jets -> A (rows m = s*8 + ch) --------
    {
        const int nc = (tid & 127) * 2;
        const int sg = tid >> 7;
        float wa0 = __ldg(&W0[nc]),     wa1 = __ldg(&W0[HID + nc]),     wa2 = __ldg(&W0[2*HID + nc]);
        float wb0 = __ldg(&W0[nc + 1]), wb1 = __ldg(&W0[HID + nc + 1]), wb2 = __ldg(&W0[2*HID + nc + 1]);
        float ba = __ldg(&b0[nc]), bb = __ldg(&b0[nc + 1]);
        #pragma unroll
        for (int i = 0; i < 4; i++) {
            int s = sg * 4 + i;
            int idx = base + s; if (idx >= B) idx = B - 1;
            float x0 = __ldg(&x[idx*3]), x1 = __ldg(&x[idx*3+1]), x2 = __ldg(&x[idx*3+2]);
            float za = fmaf(x2, wa2, fmaf(x1, wa1, fmaf(x0, wa0, ba)));
            float zb = fmaf(x2, wb2, fmaf(x1, wb1, fmaf(x0, wb0, bb)));
            float hA = my_tanhf(za), tA = 1.f - hA*hA, cA = -2.f*hA*tA;
            float hB = my_tanhf(zb), tB = 1.f - hB*hB, cB = -2.f*hB*tB;
            float va[8] = {hA, tA*wa0, tA*wa1, tA*wa2, cA*wa0*wa0, cA*wa1*wa1, cA*wa2*wa2, 0.f};
            float vb[8] = {hB, tB*wb0, tB*wb1, tB*wb2, cB*wb0*wb0, cB*wb1*wb1, cB*wb2*wb2, 0.f};
            #pragma unroll
            for (int c = 0; c < 8; c++) storeA(smem, s * 8 + c, nc, va[c], vb[c]);
        }
    }
    __syncthreads();

    // warp tiling: warp = m32 x n64  (mt = wid&1, ntq = wid>>1)
    const int mt  = wid & 1;
    const int ntq = wid >> 1;
    const int mrow0 = mt * 32;
    const int ncol0 = ntq * 64;
    const int ch = lane >> 2;
    const int srcb = lane & 3;
    const uint32_t aOff = (uint32_t)((mrow0 + (lane & 15)) * RSA + (lane >> 4) * 16);

    #pragma unroll 1
    for (int l = 0; l < 3; l++) {
        float acc[2][8][4];
        #pragma unroll
        for (int t = 0; t < 2; t++)
            #pragma unroll
            for (int nt = 0; nt < 8; nt++)
                { acc[t][nt][0]=0.f; acc[t][nt][1]=0.f; acc[t][nt][2]=0.f; acc[t][nt][3]=0.f; }

        const uint4* fH = g_wfrag + (uint32_t)(l * 4 + ntq) * 2048 + lane;

        #pragma unroll 2
        for (int ki = 0; ki < 16; ki++) {
            // A fragments (k16) for both m16 tiles, hi and lo planes
            uint32_t ah[2][4], al[2][4];
            const uint32_t akb = (uint32_t)(ki * 32);
            #pragma unroll
            for (int t = 0; t < 2; t++) {
                ldsm_x4(sb + SM_AH + aOff + (uint32_t)(t * 16 * RSA) + akb, ah[t]);
                ldsm_x4(sb + SM_AL + aOff + (uint32_t)(t * 16 * RSA) + akb, al[t]);
            }
            // B fragments via coalesced LDG.128 (L2-resident, fragment layout)
            uint4 bh[4];
            #pragma unroll
            for (int p = 0; p < 4; p++)
                bh[p] = __ldg(fH + (ki * 4 + p) * 32);
            // term-major: 8 independent accumulators between revisits
            #pragma unroll
            for (int p = 0; p < 4; p++)
                #pragma unroll
                for (int t = 0; t < 2; t++) {
                    mma16816(acc[t][2*p],   ah[t], bh[p].x, bh[p].y);
                    mma16816(acc[t][2*p+1], ah[t], bh[p].z, bh[p].w);
                }
            #pragma unroll
            for (int p = 0; p < 4; p++)
                #pragma unroll
                for (int t = 0; t < 2; t++) {
                    mma16816(acc[t][2*p],   al[t], bh[p].x, bh[p].y);
                    mma16816(acc[t][2*p+1], al[t], bh[p].z, bh[p].w);
                }
        }
        __syncthreads();   // all MMA reads of A done before epilogue overwrites A

        // -------- epilogue: z-jets -> activation jets --------
        const float* bp = (l == 0) ? b1 : (l == 1) ? b2 : b3;
        float accO[2][2] = {{0.f, 0.f}, {0.f, 0.f}};
        const int gsrc = (lane - 12) & 31;

        #pragma unroll
        for (int t = 0; t < 2; t++) {
            #pragma unroll
            for (int nt = 0; nt < 8; nt++) {
                int ncol = ncol0 + nt * 8 + (srcb << 1);
                float z0 = acc[t][nt][0], z1 = acc[t][nt][1];
                float z2 = acc[t][nt][2], z3 = acc[t][nt][3];
                float bi0 = __ldg(&bp[ncol]), bi1 = __ldg(&bp[ncol + 1]);
                float zb0 = __shfl_sync(0xffffffffu, z0, srcb) + bi0;
                float zb1 = __shfl_sync(0xffffffffu, z1, srcb) + bi1;
                float zb2 = __shfl_sync(0xffffffffu, z2, srcb) + bi0;
                float zb3 = __shfl_sync(0xffffffffu, z3, srcb) + bi1;
                float h0 = my_tanhf(zb0), t0 = 1.f - h0*h0, c0 = -2.f*h0*t0;
                float h1 = my_tanhf(zb1), t1 = 1.f - h1*h1, c1 = -2.f*h1*t1;
                float h2 = my_tanhf(zb2), t2 = 1.f - h2*h2, c2 = -2.f*h2*t2;
                float h3 = my_tanhf(zb3), t3 = 1.f - h3*h3, c3 = -2.f*h3*t3;
                float zg0 = __shfl_sync(0xffffffffu, z0, gsrc);
                float zg1 = __shfl_sync(0xffffffffu, z1, gsrc);
                float zg2 = __shfl_sync(0xffffffffu, z2, gsrc);
                float zg3 = __shfl_sync(0xffffffffu, z3, gsrc);
                float o0 = (ch == 0) ? h0 : (ch < 4) ? t0 * z0
                         : (ch < 7) ? fmaf(c0 * zg0, zg0, t0 * z0) : 0.f;
                float o1 = (ch == 0) ? h1 : (ch < 4) ? t1 * z1
                         : (ch < 7) ? fmaf(c1 * zg1, zg1, t1 * z1) : 0.f;
                float o2 = (ch == 0) ? h2 : (ch < 4) ? t2 * z2
                         : (ch < 7) ? fmaf(c2 * zg2, zg2, t2 * z2) : 0.f;
                float o3 = (ch == 0) ? h3 : (ch < 4) ? t3 * z3
                         : (ch < 7) ? fmaf(c3 * zg3, zg3, t3 * z3) : 0.f;
                if (l < 2) {
                    storeA(smem, mrow0 + t * 16 + ch,     ncol, o0, o1);
                    storeA(smem, mrow0 + t * 16 + ch + 8, ncol, o2, o3);
                } else {
                    float w0 = __ldg(&Wout[ncol]), w1 = __ldg(&Wout[ncol + 1]);
                    accO[t][0] = fmaf(o0, w0, fmaf(o1, w1, accO[t][0]));
                    accO[t][1] = fmaf(o2, w0, fmaf(o3, w1, accO[t][1]));
                }
            }
        }

        if (l < 2) {
            __syncthreads();   // A stores visible before next layer's LDSM
        } else {
            #pragma unroll
            for (int t = 0; t < 2; t++) {
                accO[t][0] += __shfl_xor_sync(0xffffffffu, accO[t][0], 1);
                accO[t][0] += __shfl_xor_sync(0xffffffffu, accO[t][0], 2);
                accO[t][1] += __shfl_xor_sync(0xffffffffu, accO[t][1], 1);
                accO[t][1] += __shfl_xor_sync(0xffffffffu, accO[t][1], 2);
            }
            float* red = (float*)(smem + SM_RED);
            if (srcb == 0) {
                #pragma unroll
                for (int t = 0; t < 2; t++) {
                    red[ntq * 64 + mrow0 + t * 16 + ch]     = accO[t][0];
                    red[ntq * 64 + mrow0 + t * 16 + ch + 8] = accO[t][1];
                }
            }
            __syncthreads();
            if (tid < 64) {
                float v = red[tid] + red[64 + tid] + red[128 + tid] + red[192 + tid];
                int s = tid >> 3, c = tid & 7;
                int g = base + s;
                if (c < 7 && g < B) {
                    if (c == 0) v += __ldg(&bout[0]);
                    out[g * 7 + c] = v;
                }
            }
        }
    }
}

extern "C" void kernel_launch(void* const* d_in, const int* in_sizes, int n_in,
                              void* d_out, int out_size)
{
    const float* x    = (const float*)d_in[0];
    const float* W0   = (const float*)d_in[1];
    const float* b0   = (const float*)d_in[2];
    const float* W1   = (const float*)d_in[3];
    const float* b1   = (const float*)d_in[4];
    const float* W2   = (const float*)d_in[5];
    const float* b2   = (const float*)d_in[6];
    const float* W3   = (const float*)d_in[7];
    const float* b3   = (const float*)d_in[8];
    const float* Wout = (const float*)d_in[9];
    const float* bout = (const float*)d_in[10];
    float* out = (float*)d_out;

    const int B = in_sizes[0] / 3;
    const int nblk = (B + SPB - 1) / SPB;

    prep_w_kernel<<<(3 * 32768 + 255) / 256, 256>>>(W1, W2, W3);

    cudaFuncSetAttribute(pinn_mma_kernel,
                         cudaFuncAttributeMaxDynamicSharedMemorySize, SMEM_TOTAL);
    pinn_mma_kernel<<<nblk, TPB, SMEM_TOTAL>>>(x, W0, b0, b1, b2, b3,
                                               Wout, bout, out, B);
}